// round 11
// baseline (speedup 1.0000x reference)
#include <cuda_runtime.h>
#include <math.h>

#define N 2048
#define IN_DIM 128
#define OUT_DIM 32
#define ROWS 8
#define NWARPS 8
#define TABSZ 512
#define JSPLIT 8
#define JCHUNK (N / JSPLIT)          // 256 j's per block
#define NBATCH (JCHUNK / 32)         // 8 batches: one per warp
#define NGROUPS (N / ROWS)           // 256 row-groups

#define PREP_BLKS (N / 16)                       // 128 (16 rows/block)
#define TAB_BLKS  ((TABSZ + 1 + 7) / 8)          // 65 (8 q's per block)

// Scratch (allocation-free rule: __device__ globals)
__device__ float g_z[N * OUT_DIM];
__device__ float g_src[N];
__device__ float g_dst[N];
__device__ float g_val[TABSZ + 1];
__device__ float g_maxdst = -1e30f;   // reset by combine each run (graph-safe)
__device__ float g_maxg   = -1e30f;
__device__ float g_pl[N * JSPLIT];               // partial softmax denominators
__device__ float g_pa[N * JSPLIT * OUT_DIM];     // partial att@z accumulators

__device__ __forceinline__ float atomicMaxFloat(float* addr, float value) {
    return (value >= 0.f)
        ? __int_as_float(atomicMax((int*)addr, __float_as_int(value)))
        : __uint_as_float(atomicMin((unsigned*)addr, __float_as_uint(value)));
}

__device__ __forceinline__ void cp16(void* smem, const void* gmem) {
    unsigned s = (unsigned)__cvta_generic_to_shared(smem);
    asm volatile("cp.async.ca.shared.global [%0], [%1], 16;" :: "r"(s), "l"(gmem));
}
#define CP_COMMIT() asm volatile("cp.async.commit_group;")
#define CP_WAIT0()  asm volatile("cp.async.wait_group 0;")

// ---------------------------------------------------------------------------
// Fused prologue (unchanged from R10 — measured good).
// Blocks [0,128): z = feat@W for 16 rows/block, W+feat cp.async-staged,
// each warp computes 2 rows x 32 cols from smem. Also src/dst + dst-max.
// Blocks [128, 128+65): e_time lookup table (+ table max atomic).
// ---------------------------------------------------------------------------
__global__ void __launch_bounds__(256)
prep_kernel(const float* __restrict__ feat,
            const float* __restrict__ a,
            const float* __restrict__ W,
            const int*   __restrict__ te,
            const float* __restrict__ bf) {
    const int warp = threadIdx.x >> 5;
    const int lane = threadIdx.x & 31;
    __shared__ float s_W[IN_DIM * OUT_DIM];      // 16 KB
    __shared__ float s_feat[16 * IN_DIM];        // 8 KB
    __shared__ float s_red[8];

    if (blockIdx.x < PREP_BLKS) {
#pragma unroll
        for (int t = 0; t < 4; ++t) {
            int seg = threadIdx.x + 256 * t;
            cp16((char*)s_W + seg * 16, (const char*)W + seg * 16);
        }
        {
            const char* fsrc = (const char*)(feat + blockIdx.x * 16 * IN_DIM);
#pragma unroll
            for (int t = 0; t < 2; ++t) {
                int seg = threadIdx.x + 256 * t;
                cp16((char*)s_feat + seg * 16, fsrc + seg * 16);
            }
        }
        CP_COMMIT();
        CP_WAIT0();
        __syncthreads();

        const int   r0 = 2 * warp;
        const float4* f0 = (const float4*)(s_feat + r0 * IN_DIM);
        const float4* f1 = (const float4*)(s_feat + (r0 + 1) * IN_DIM);
        float b00 = 0.f, b01 = 0.f, b10 = 0.f, b11 = 0.f;
#pragma unroll
        for (int d4 = 0; d4 < IN_DIM / 4; ++d4) {
            float4 x0 = f0[d4];                  // broadcast LDS.128
            float4 x1 = f1[d4];
            float w0 = s_W[(d4 * 4 + 0) * OUT_DIM + lane];  // bank = lane
            float w1 = s_W[(d4 * 4 + 1) * OUT_DIM + lane];
            float w2 = s_W[(d4 * 4 + 2) * OUT_DIM + lane];
            float w3 = s_W[(d4 * 4 + 3) * OUT_DIM + lane];
            b00 = fmaf(x0.x, w0, b00);  b01 = fmaf(x0.y, w1, b01);
            b00 = fmaf(x0.z, w2, b00);  b01 = fmaf(x0.w, w3, b01);
            b10 = fmaf(x1.x, w0, b10);  b11 = fmaf(x1.y, w1, b11);
            b10 = fmaf(x1.z, w2, b10);  b11 = fmaf(x1.w, w3, b11);
        }
        const float z0 = b00 + b01;
        const float z1 = b10 + b11;
        const int i0 = blockIdx.x * 16 + r0;
        g_z[(i0 + 0) * OUT_DIM + lane] = z0;
        g_z[(i0 + 1) * OUT_DIM + lane] = z1;

        const float a1 = a[lane], a2 = a[OUT_DIM + lane];
        float s0 = z0 * a1, t0 = z0 * a2;
        float s1 = z1 * a1, t1 = z1 * a2;
#pragma unroll
        for (int o = 16; o > 0; o >>= 1) {
            s0 += __shfl_xor_sync(0xffffffffu, s0, o);
            t0 += __shfl_xor_sync(0xffffffffu, t0, o);
            s1 += __shfl_xor_sync(0xffffffffu, s1, o);
            t1 += __shfl_xor_sync(0xffffffffu, t1, o);
        }
        if (lane == 0) {
            g_src[i0 + 0] = s0;  g_dst[i0 + 0] = t0;
            g_src[i0 + 1] = s1;  g_dst[i0 + 1] = t1;
            s_red[warp] = fmaxf(t0, t1);
        }
        __syncthreads();
        if (threadIdx.x == 0) {
            float md = s_red[0];
#pragma unroll
            for (int w = 1; w < 8; ++w) md = fmaxf(md, s_red[w]);
            atomicMaxFloat(&g_maxdst, md);
        }
    } else {
        const int q = (blockIdx.x - PREP_BLKS) * 8 + warp;
        float v = -1e30f;
        if (q <= TABSZ) {
            int ti = *te;
            float T = (ti > -1000000 && ti < 1000000) ? (float)ti
                                                      : __int_as_float(ti);
            float tsv = (float)q / (float)TABSZ;
            float dt  = T - tsv;
            float th  = dt * bf[lane];
            v = a[2 * lane] * sinf(th) + a[2 * lane + 1] * cosf(th);
#pragma unroll
            for (int o = 16; o > 0; o >>= 1)
                v += __shfl_xor_sync(0xffffffffu, v, o);
            if (lane == 0) g_val[q] = v;
        }
        if (lane == 0) s_red[warp] = v;
        __syncthreads();
        if (threadIdx.x == 0) {
            float mg = s_red[0];
#pragma unroll
            for (int w = 1; w < 8; ++w) mg = fmaxf(mg, s_red[w]);
            atomicMaxFloat(&g_maxg, mg);
        }
    }
}

// ---------------------------------------------------------------------------
// Fused attention. grid = (NGROUPS, JSPLIT) = (256, 8) -> 2048 short blocks.
// Each warp owns exactly ONE 32-j batch (no loop): score 8 rows lane-parallel
// with fixed softmax shift, then PV via smem-staged p + broadcast LDS.128.
// ---------------------------------------------------------------------------
__global__ void __launch_bounds__(256)
attn_kernel(const int*   __restrict__ adj,
            const float* __restrict__ ts) {
    __shared__ float2 s_tab[TABSZ];                       // 4 KB
    __shared__ float  sm_p[NWARPS][32][ROWS];             // 8 KB
    __shared__ float  sm_l[ROWS][NWARPS];
    __shared__ float  sm_a[ROWS][NWARPS][OUT_DIM];        // 8 KB

    const int i0    = blockIdx.x * ROWS;
    const int split = blockIdx.y;
    const int jbase = split * JCHUNK;
    const int warp  = threadIdx.x >> 5;
    const int lane  = threadIdx.x & 31;

    for (int q = threadIdx.x; q < TABSZ; q += 256)
        s_tab[q] = make_float2(g_val[q], g_val[q + 1]);
    __syncthreads();

    const float MB = g_maxdst + g_maxg;
    float src[ROWS], m[ROWS], l[ROWS], acc[ROWS];
#pragma unroll
    for (int r = 0; r < ROWS; ++r) {
        src[r] = g_src[i0 + r];
        float U = src[r] + MB;
        m[r] = fmaxf(U, 0.05f * U);   // leaky of the raw upper bound
        l[r] = 0.f;  acc[r] = 0.f;
    }

    // One batch per warp.
    {
        const int bb = warp;
        const int j  = jbase + bb * 32 + lane;
        const float dstj = g_dst[j];
        float p[ROWS];
#pragma unroll
        for (int r = 0; r < ROWS; ++r) {
            const int   row = i0 + r;
            const int   av  = adj[row * N + j];
            const float t_  = ts [row * N + j];
            float qf = t_ * (float)TABSZ;          // ts in [0,1)
            int   qi = __float2int_rz(qf);
            float fr = qf - (float)qi;
            float2 tt = s_tab[qi];
            float g  = fmaf(fr, tt.y - tt.x, tt.x);
            float e  = src[r] + dstj + g;
            e = fmaxf(e, 0.05f * e);               // leaky relu
            e = (av > 0) ? (e - m[r]) : -1e30f;    // mask -> p = 0
            p[r] = __expf(e);
            l[r] += p[r];
        }
        // Stage p tile to smem: 2x STS.128 per lane
        float4* pd = (float4*)&sm_p[warp][lane][0];
        pd[0] = make_float4(p[0], p[1], p[2], p[3]);
        pd[1] = make_float4(p[4], p[5], p[6], p[7]);
        __syncwarp();

        const float* zb = g_z + (jbase + bb * 32) * OUT_DIM;
#pragma unroll
        for (int jj = 0; jj < 32; ++jj) {
            float zv = zb[jj * OUT_DIM + lane];    // coalesced 128B, L2-hit
            const float4* ps = (const float4*)&sm_p[warp][jj][0];
            float4 p03 = ps[0];                    // broadcast LDS.128
            float4 p47 = ps[1];
            acc[0] = fmaf(p03.x, zv, acc[0]);
            acc[1] = fmaf(p03.y, zv, acc[1]);
            acc[2] = fmaf(p03.z, zv, acc[2]);
            acc[3] = fmaf(p03.w, zv, acc[3]);
            acc[4] = fmaf(p47.x, zv, acc[4]);
            acc[5] = fmaf(p47.y, zv, acc[5]);
            acc[6] = fmaf(p47.z, zv, acc[6]);
            acc[7] = fmaf(p47.w, zv, acc[7]);
        }
    }

    // Reduce l within warp; stash partials for cross-warp combine.
#pragma unroll
    for (int r = 0; r < ROWS; ++r) {
        float lv = l[r];
#pragma unroll
        for (int o = 16; o > 0; o >>= 1)
            lv += __shfl_xor_sync(0xffffffffu, lv, o);
        if (lane == 0) sm_l[r][warp] = lv;
        sm_a[r][warp][lane] = acc[r];
    }
    __syncthreads();

    // Warp r writes partial for row i0+r, this split.
    {
        const int r = warp;
        const int i = i0 + r;
        float L = 0.f, A = 0.f;
#pragma unroll
        for (int w = 0; w < NWARPS; ++w) {
            L += sm_l[r][w];
            A += sm_a[r][w][lane];
        }
        g_pa[(i * JSPLIT + split) * OUT_DIM + lane] = A;
        if (lane == 0) g_pl[i * JSPLIT + split] = L;
    }
}

// ---------------------------------------------------------------------------
// Combine partials + residual + layernorm. One warp per row.
// Also resets the max cells for the next graph replay.
// ---------------------------------------------------------------------------
__global__ void __launch_bounds__(256)
combine_kernel(const float* __restrict__ gamma,
               const float* __restrict__ beta,
               float*       __restrict__ out) {
    const int warp = threadIdx.x >> 5;
    const int lane = threadIdx.x & 31;
    const int i = blockIdx.x * 8 + warp;

    float A = 0.f, L = 0.f;
#pragma unroll
    for (int s = 0; s < JSPLIT; ++s) {
        A += g_pa[(i * JSPLIT + s) * OUT_DIM + lane];
        L += g_pl[i * JSPLIT + s];
    }
    float temp = A / L + g_z[i * OUT_DIM + lane];

    float mu = temp;
#pragma unroll
    for (int o = 16; o > 0; o >>= 1) mu += __shfl_xor_sync(0xffffffffu, mu, o);
    mu *= (1.0f / OUT_DIM);
    float d = temp - mu;
    float v = d * d;
#pragma unroll
    for (int o = 16; o > 0; o >>= 1) v += __shfl_xor_sync(0xffffffffu, v, o);
    v *= (1.0f / OUT_DIM);
    out[i * OUT_DIM + lane] = d * rsqrtf(v + 1e-6f) * gamma[lane] + beta[lane];

    if (blockIdx.x == 0 && threadIdx.x == 0) {
        g_maxdst = -1e30f;      // reset for next replay (deterministic)
        g_maxg   = -1e30f;
    }
}

// ---------------------------------------------------------------------------
extern "C" void kernel_launch(void* const* d_in, const int* in_sizes, int n_in,
                              void* d_out, int out_size) {
    const float* feat = (const float*)d_in[0];   // (2048,128) f32
    const int*   adj  = (const int*)  d_in[1];   // (2048,2048) i32
    const float* ts   = (const float*)d_in[2];   // (2048,2048) f32
    const float* a    = (const float*)d_in[3];   // (64,1) f32
    const int*   te   = (const int*)  d_in[4];   // scalar int
    const float* W    = (const float*)d_in[5];   // (128,32) f32
    const float* bf   = (const float*)d_in[6];   // (32,) f32
    const float* gam  = (const float*)d_in[7];   // (32,) f32
    const float* bet  = (const float*)d_in[8];   // (32,) f32
    float* out = (float*)d_out;                  // (2048,32) f32

    prep_kernel<<<PREP_BLKS + TAB_BLKS, 256>>>(feat, a, W, te, bf);
    dim3 grid(NGROUPS, JSPLIT);
    attn_kernel<<<grid, 256>>>(adj, ts);
    combine_kernel<<<N / 8, 256>>>(gam, bet, out);
}

// round 12
// speedup vs baseline: 1.5631x; 1.5631x over previous
#include <cuda_runtime.h>
#include <math.h>

#define N 2048
#define IN_DIM 128
#define OUT_DIM 32
#define ROWS 8
#define NWARPS 8
#define TABSZ 512
#define JSPLIT 4
#define JCHUNK (N / JSPLIT)          // 512 j's per block
#define NBATCH (JCHUNK / 32)         // 16 batches of 32 j's
#define NGROUPS (N / ROWS)           // 256 row-groups

#define PREP_BLKS (N / 16)                       // 128 (16 rows/block)
#define TAB_BLKS  ((TABSZ + 1 + 7) / 8)          // 65 (8 q's per block)

// Scratch (allocation-free rule: __device__ globals)
__device__ float g_z[N * OUT_DIM];
__device__ float g_src[N];
__device__ float g_dst[N];
__device__ float g_val[TABSZ + 1];
__device__ float g_maxdst = -1e30f;   // reset by combine each run (graph-safe)
__device__ float g_maxg   = -1e30f;
__device__ float g_pl[N * JSPLIT];               // partial softmax denominators
__device__ float g_pa[N * JSPLIT * OUT_DIM];     // partial att@z accumulators

__device__ __forceinline__ float atomicMaxFloat(float* addr, float value) {
    return (value >= 0.f)
        ? __int_as_float(atomicMax((int*)addr, __float_as_int(value)))
        : __uint_as_float(atomicMin((unsigned*)addr, __float_as_uint(value)));
}

__device__ __forceinline__ void cp16(void* smem, const void* gmem) {
    unsigned s = (unsigned)__cvta_generic_to_shared(smem);
    asm volatile("cp.async.ca.shared.global [%0], [%1], 16;" :: "r"(s), "l"(gmem));
}
#define CP_COMMIT() asm volatile("cp.async.commit_group;")
#define CP_WAIT0()  asm volatile("cp.async.wait_group 0;")

// ---------------------------------------------------------------------------
// Fused prologue (identical to R10 — measured good).
// Blocks [0,128): z = feat@W for 16 rows/block, W+feat cp.async-staged,
// each warp computes 2 rows x 32 cols from smem. Also src/dst + dst-max.
// Blocks [128, 128+65): e_time lookup table (+ table max atomic).
// ---------------------------------------------------------------------------
__global__ void __launch_bounds__(256)
prep_kernel(const float* __restrict__ feat,
            const float* __restrict__ a,
            const float* __restrict__ W,
            const int*   __restrict__ te,
            const float* __restrict__ bf) {
    const int warp = threadIdx.x >> 5;
    const int lane = threadIdx.x & 31;
    __shared__ float s_W[IN_DIM * OUT_DIM];      // 16 KB
    __shared__ float s_feat[16 * IN_DIM];        // 8 KB
    __shared__ float s_red[8];

    if (blockIdx.x < PREP_BLKS) {
#pragma unroll
        for (int t = 0; t < 4; ++t) {
            int seg = threadIdx.x + 256 * t;
            cp16((char*)s_W + seg * 16, (const char*)W + seg * 16);
        }
        {
            const char* fsrc = (const char*)(feat + blockIdx.x * 16 * IN_DIM);
#pragma unroll
            for (int t = 0; t < 2; ++t) {
                int seg = threadIdx.x + 256 * t;
                cp16((char*)s_feat + seg * 16, fsrc + seg * 16);
            }
        }
        CP_COMMIT();
        CP_WAIT0();
        __syncthreads();

        const int   r0 = 2 * warp;
        const float4* f0 = (const float4*)(s_feat + r0 * IN_DIM);
        const float4* f1 = (const float4*)(s_feat + (r0 + 1) * IN_DIM);
        float b00 = 0.f, b01 = 0.f, b10 = 0.f, b11 = 0.f;
#pragma unroll
        for (int d4 = 0; d4 < IN_DIM / 4; ++d4) {
            float4 x0 = f0[d4];                  // broadcast LDS.128
            float4 x1 = f1[d4];
            float w0 = s_W[(d4 * 4 + 0) * OUT_DIM + lane];  // bank = lane
            float w1 = s_W[(d4 * 4 + 1) * OUT_DIM + lane];
            float w2 = s_W[(d4 * 4 + 2) * OUT_DIM + lane];
            float w3 = s_W[(d4 * 4 + 3) * OUT_DIM + lane];
            b00 = fmaf(x0.x, w0, b00);  b01 = fmaf(x0.y, w1, b01);
            b00 = fmaf(x0.z, w2, b00);  b01 = fmaf(x0.w, w3, b01);
            b10 = fmaf(x1.x, w0, b10);  b11 = fmaf(x1.y, w1, b11);
            b10 = fmaf(x1.z, w2, b10);  b11 = fmaf(x1.w, w3, b11);
        }
        const float z0 = b00 + b01;
        const float z1 = b10 + b11;
        const int i0 = blockIdx.x * 16 + r0;
        g_z[(i0 + 0) * OUT_DIM + lane] = z0;
        g_z[(i0 + 1) * OUT_DIM + lane] = z1;

        const float a1 = a[lane], a2 = a[OUT_DIM + lane];
        float s0 = z0 * a1, t0 = z0 * a2;
        float s1 = z1 * a1, t1 = z1 * a2;
#pragma unroll
        for (int o = 16; o > 0; o >>= 1) {
            s0 += __shfl_xor_sync(0xffffffffu, s0, o);
            t0 += __shfl_xor_sync(0xffffffffu, t0, o);
            s1 += __shfl_xor_sync(0xffffffffu, s1, o);
            t1 += __shfl_xor_sync(0xffffffffu, t1, o);
        }
        if (lane == 0) {
            g_src[i0 + 0] = s0;  g_dst[i0 + 0] = t0;
            g_src[i0 + 1] = s1;  g_dst[i0 + 1] = t1;
            s_red[warp] = fmaxf(t0, t1);
        }
        __syncthreads();
        if (threadIdx.x == 0) {
            float md = s_red[0];
#pragma unroll
            for (int w = 1; w < 8; ++w) md = fmaxf(md, s_red[w]);
            atomicMaxFloat(&g_maxdst, md);
        }
    } else {
        const int q = (blockIdx.x - PREP_BLKS) * 8 + warp;
        float v = -1e30f;
        if (q <= TABSZ) {
            int ti = *te;
            float T = (ti > -1000000 && ti < 1000000) ? (float)ti
                                                      : __int_as_float(ti);
            float tsv = (float)q / (float)TABSZ;
            float dt  = T - tsv;
            float th  = dt * bf[lane];
            v = a[2 * lane] * sinf(th) + a[2 * lane + 1] * cosf(th);
#pragma unroll
            for (int o = 16; o > 0; o >>= 1)
                v += __shfl_xor_sync(0xffffffffu, v, o);
            if (lane == 0) g_val[q] = v;
        }
        if (lane == 0) s_red[warp] = v;
        __syncthreads();
        if (threadIdx.x == 0) {
            float mg = s_red[0];
#pragma unroll
            for (int w = 1; w < 8; ++w) mg = fmaxf(mg, s_red[w]);
            atomicMaxFloat(&g_maxg, mg);
        }
    }
}

// ---------------------------------------------------------------------------
// Fused attention (R10/R5 structure; src/m in smem to cut regs; 5 blocks/SM).
// grid = (NGROUPS, JSPLIT) = (256, 4). Lane-parallel scores (lane = j);
// fixed softmax shift m_i; PV via smem-staged p + broadcast LDS.128.
// ---------------------------------------------------------------------------
__global__ void __launch_bounds__(256, 5)
attn_kernel(const int*   __restrict__ adj,
            const float* __restrict__ ts) {
    __shared__ float2 s_tab[TABSZ];                       // 4 KB
    __shared__ float2 s_row[ROWS];                        // (src, m) per row
    __shared__ float  sm_p[NWARPS][32][ROWS];             // 8 KB
    __shared__ float  sm_l[ROWS][NWARPS];
    __shared__ float  sm_a[ROWS][NWARPS][OUT_DIM];        // 8 KB

    const int i0    = blockIdx.x * ROWS;
    const int split = blockIdx.y;
    const int jbase = split * JCHUNK;
    const int warp  = threadIdx.x >> 5;
    const int lane  = threadIdx.x & 31;

    for (int q = threadIdx.x; q < TABSZ; q += 256)
        s_tab[q] = make_float2(g_val[q], g_val[q + 1]);
    if (threadIdx.x < ROWS) {
        float s = g_src[i0 + threadIdx.x];
        float U = s + g_maxdst + g_maxg;
        s_row[threadIdx.x] = make_float2(s, fmaxf(U, 0.05f * U));
    }
    __syncthreads();

    float l[ROWS], acc[ROWS];
#pragma unroll
    for (int r = 0; r < ROWS; ++r) { l[r] = 0.f; acc[r] = 0.f; }

    for (int bb = warp; bb < NBATCH; bb += NWARPS) {
        const int j = jbase + bb * 32 + lane;
        const float dstj = g_dst[j];
        float p[ROWS];
#pragma unroll
        for (int r = 0; r < ROWS; ++r) {
            float2 sr = s_row[r];                  // (src, m) broadcast LDS
            const int   av  = adj[(i0 + r) * N + j];
            const float t_  = ts [(i0 + r) * N + j];
            float qf = t_ * (float)TABSZ;          // ts in [0,1)
            int   qi = __float2int_rz(qf);
            float fr = qf - (float)qi;
            float2 tt = s_tab[qi];
            float g  = fmaf(fr, tt.y - tt.x, tt.x);
            float e  = sr.x + dstj + g;
            e = fmaxf(e, 0.05f * e);               // leaky relu
            e = (av > 0) ? (e - sr.y) : -1e30f;    // mask -> p = 0
            p[r] = __expf(e);
            l[r] += p[r];
        }
        // Stage p tile to smem: 2x STS.128 per lane
        float4* pd = (float4*)&sm_p[warp][lane][0];
        pd[0] = make_float4(p[0], p[1], p[2], p[3]);
        pd[1] = make_float4(p[4], p[5], p[6], p[7]);
        __syncwarp();

        const float* zb = g_z + (jbase + bb * 32) * OUT_DIM;
#pragma unroll
        for (int jj = 0; jj < 32; ++jj) {
            float zv = zb[jj * OUT_DIM + lane];    // coalesced 128B, L2-hit
            const float4* ps = (const float4*)&sm_p[warp][jj][0];
            float4 p03 = ps[0];                    // broadcast LDS.128
            float4 p47 = ps[1];
            acc[0] = fmaf(p03.x, zv, acc[0]);
            acc[1] = fmaf(p03.y, zv, acc[1]);
            acc[2] = fmaf(p03.z, zv, acc[2]);
            acc[3] = fmaf(p03.w, zv, acc[3]);
            acc[4] = fmaf(p47.x, zv, acc[4]);
            acc[5] = fmaf(p47.y, zv, acc[5]);
            acc[6] = fmaf(p47.z, zv, acc[6]);
            acc[7] = fmaf(p47.w, zv, acc[7]);
        }
        __syncwarp();
    }

    // Reduce l within warp; stash partials for cross-warp combine.
#pragma unroll
    for (int r = 0; r < ROWS; ++r) {
        float lv = l[r];
#pragma unroll
        for (int o = 16; o > 0; o >>= 1)
            lv += __shfl_xor_sync(0xffffffffu, lv, o);
        if (lane == 0) sm_l[r][warp] = lv;
        sm_a[r][warp][lane] = acc[r];
    }
    __syncthreads();

    // Warp r writes partial for row i0+r, this split.
    {
        const int r = warp;
        const int i = i0 + r;
        float L = 0.f, A = 0.f;
#pragma unroll
        for (int w = 0; w < NWARPS; ++w) {
            L += sm_l[r][w];
            A += sm_a[r][w][lane];
        }
        g_pa[(i * JSPLIT + split) * OUT_DIM + lane] = A;
        if (lane == 0) g_pl[i * JSPLIT + split] = L;
    }
}

// ---------------------------------------------------------------------------
// Combine partials + residual + layernorm (identical to R10). One warp/row.
// Also resets the max cells for the next graph replay.
// ---------------------------------------------------------------------------
__global__ void __launch_bounds__(256)
combine_kernel(const float* __restrict__ gamma,
               const float* __restrict__ beta,
               float*       __restrict__ out) {
    const int warp = threadIdx.x >> 5;
    const int lane = threadIdx.x & 31;
    const int i = blockIdx.x * 8 + warp;

    float A = 0.f, L = 0.f;
#pragma unroll
    for (int s = 0; s < JSPLIT; ++s) {
        A += g_pa[(i * JSPLIT + s) * OUT_DIM + lane];
        L += g_pl[i * JSPLIT + s];
    }
    float temp = A / L + g_z[i * OUT_DIM + lane];

    float mu = temp;
#pragma unroll
    for (int o = 16; o > 0; o >>= 1) mu += __shfl_xor_sync(0xffffffffu, mu, o);
    mu *= (1.0f / OUT_DIM);
    float d = temp - mu;
    float v = d * d;
#pragma unroll
    for (int o = 16; o > 0; o >>= 1) v += __shfl_xor_sync(0xffffffffu, v, o);
    v *= (1.0f / OUT_DIM);
    out[i * OUT_DIM + lane] = d * rsqrtf(v + 1e-6f) * gamma[lane] + beta[lane];

    if (blockIdx.x == 0 && threadIdx.x == 0) {
        g_maxdst = -1e30f;      // reset for next replay (deterministic)
        g_maxg   = -1e30f;
    }
}

// ---------------------------------------------------------------------------
extern "C" void kernel_launch(void* const* d_in, const int* in_sizes, int n_in,
                              void* d_out, int out_size) {
    const float* feat = (const float*)d_in[0];   // (2048,128) f32
    const int*   adj  = (const int*)  d_in[1];   // (2048,2048) i32
    const float* ts   = (const float*)d_in[2];   // (2048,2048) f32
    const float* a    = (const float*)d_in[3];   // (64,1) f32
    const int*   te   = (const int*)  d_in[4];   // scalar int
    const float* W    = (const float*)d_in[5];   // (128,32) f32
    const float* bf   = (const float*)d_in[6];   // (32,) f32
    const float* gam  = (const float*)d_in[7];   // (32,) f32
    const float* bet  = (const float*)d_in[8];   // (32,) f32
    float* out = (float*)d_out;                  // (2048,32) f32

    prep_kernel<<<PREP_BLKS + TAB_BLKS, 256>>>(feat, a, W, te, bf);
    dim3 grid(NGROUPS, JSPLIT);
    attn_kernel<<<grid, 256>>>(adj, ts);
    combine_kernel<<<N / 8, 256>>>(gam, bet, out);
}